// round 13
// baseline (speedup 1.0000x reference)
#include <cuda_runtime.h>
#include <math.h>

#define NVEH 8192
#define NT   512
#define VPC  64           // vehicles per CTA (one CTA per SM)
#define TPB  640          // 20 warps; 10 threads per vehicle
#define XSTR 36           // smem row stride (floats), 16B aligned
#define GRID (NVEH / VPC) // 128

typedef unsigned long long ull;

// ---------------- packed f32x2 helpers (sm_103a) ----------------
__device__ __forceinline__ ull fma2(ull a, ull b, ull c){
    ull d;
    asm("fma.rn.f32x2 %0, %1, %2, %3;" : "=l"(d) : "l"(a), "l"(b), "l"(c));
    return d;
}
__device__ __forceinline__ ull pack2(float a, float b){
    ull d; asm("mov.b64 %0, {%1, %2};" : "=l"(d) : "f"(a), "f"(b)); return d;
}
__device__ __forceinline__ float2 unpack2(ull a){
    float2 r; asm("mov.b64 {%0, %1}, %2;" : "=f"(r.x), "=f"(r.y) : "l"(a)); return r;
}
__device__ __forceinline__ float hadd2(ull a){
    float2 r = unpack2(a); return r.x + r.y;
}

// ---------------- activations: single-MUFU tanh ----------------
__device__ __forceinline__ float tanh_f(float x){
    float y; asm("tanh.approx.f32 %0, %1;" : "=f"(y) : "f"(x)); return y;
}
__device__ __forceinline__ float sigt(float x){
    return fmaf(0.5f, tanh_f(0.5f * x), 0.5f);
}
__device__ __forceinline__ float nanfix(float x){
    unsigned uu = __float_as_uint(x);
    return ((uu & 0x7fffffffu) > 0x7f800000u) ? 1.0f : x;
}

// transform one raw float4 chunk of leadfol input into model features
__device__ __forceinline__ float4 xform(float4 e, float pos, int xc){
    float4 xo;
    if (xc == 0){
        xo.x = (e.x - pos) * 0.01f; xo.y = (e.y - pos) * 0.01f;
        xo.z = (e.z - pos) * 0.01f; xo.w = (pos - e.w) * 0.01f;
    } else if (xc == 1){
        xo.x = (pos - e.x) * 0.01f; xo.y = (pos - e.y) * 0.01f;
        xo.z = e.z * 0.025f;        xo.w = e.w * 0.025f;
    } else {
        xo.x = e.x * 0.025f; xo.y = e.y * 0.025f;
        xo.z = e.z * 0.025f; xo.w = e.w * 0.025f;
    }
    xo.x = nanfix(xo.x); xo.y = nanfix(xo.y);
    xo.z = nanfix(xo.z); xo.w = nanfix(xo.w);
    return xo;
}

__global__ __launch_bounds__(TPB, 1)
void lstm_kernel(
    const float* __restrict__ lf,   // (8192,512,12)
    const float* __restrict__ tt,   // (8192,512)
    const float* __restrict__ hs,   // (2,8192,20)
    const float* __restrict__ Wk,   // (12,80)
    const float* __restrict__ Wr,   // (20,80)
    const float* __restrict__ bl,   // (80)
    const float* __restrict__ Wd,   // (20,10)
    const float* __restrict__ bd,   // (10)
    const float* __restrict__ Wlc,  // (10,3)
    const float* __restrict__ blc,  // (3)
    float* __restrict__ out)
{
    __shared__ float sX[2][VPC][XSTR];   // [0..11]=x_t, [12..31]=h_{t-1}
    __shared__ ull   sWz[16][80];        // packed k-rowpair weights, col cp = u*4 + gate
    __shared__ ull   sWdP[10][10];       // packed dense weights [rowpair][col]
    __shared__ float sbd[10];
    __shared__ float sWlc[30];
    __shared__ float sblc[3];

    const int tid = threadIdx.x;
    const int blk = blockIdx.x;
    const int vb  = blk * VPC;

    // ---- one-time shared init ----
    for (int idx = tid; idx < 16*80; idx += TPB){
        int rp = idx / 80, cp = idx % 80;
        int uu = cp >> 2, gg = cp & 3;
        int oc = gg*20 + uu;                // keras gate order i,f,c,o
        int k0 = 2*rp, k1 = 2*rp + 1;
        float w0 = (k0 < 12) ? Wk[k0*80 + oc] : Wr[(k0-12)*80 + oc];
        float w1 = (k1 < 12) ? Wk[k1*80 + oc] : Wr[(k1-12)*80 + oc];
        sWz[rp][cp] = pack2(w0, w1);
    }
    for (int idx = tid; idx < 100; idx += TPB){
        int rp = idx / 10, cc = idx % 10;
        sWdP[rp][cc] = pack2(Wd[(2*rp)*10 + cc], Wd[(2*rp+1)*10 + cc]);
    }
    for (int idx = tid; idx < 10; idx += TPB) sbd[idx]  = bd[idx];
    for (int idx = tid; idx < 30; idx += TPB) sWlc[idx] = Wlc[idx];
    for (int idx = tid; idx < 3;  idx += TPB) sblc[idx] = blc[idx];
    // initial h into buf0
    for (int idx = tid; idx < VPC*20; idx += TPB){
        int v = idx / 20, k = idx % 20;
        sX[0][v][12 + k] = hs[((size_t)(vb + v))*20 + k];
    }

    // ---- per-thread identities ----
    // z (all 640 threads): 320 slots x 2 k-halves
    const int half = tid & 1;        // k-half: 0 -> rows 0..15, 1 -> rows 16..31
    const int s    = tid >> 1;       // slot 0..319
    const int u    = s % 20;         // unit
    const int g    = s / 20;         // vehicle group 0..15, vehicles 4g..4g+3
    // aux roles by decade: d = vehicle, r = role within decade
    const int d    = tid / 10;       // 0..63
    const int r    = tid - 10*d;     // 0..9
    const int lane = tid & 31;
    // loaders: r in {0,1,2} -> x chunk r of vehicle d
    const int  xc = r;
    const bool is_loader = (r < 3);
    // dense: r in {4,5} -> half dh of vehicle d's dense cols; pair (10d+4,10d+5)
    const int  dh = r - 4;
    const bool is_dense = (r == 4 || r == 5);
    const int  dpartner = lane + (r == 4 ? 1 : -1);   // partner lane for shfl

    // x(t=0) staged into buf0
    if (is_loader){
        const float4 e = *reinterpret_cast<const float4*>(
            lf + ((size_t)(vb + d) * NT) * 12 + 4*xc);
        float pos = (xc < 2) ? tt[(size_t)(vb + d) * NT] : 0.0f;
        *reinterpret_cast<float4*>(&sX[0][d][4*xc]) = xform(e, pos, xc);
    }
    __syncthreads();

    // ---- this thread's half of the z weights (32 b64) ----
    ull wreg[8][4];
    #pragma unroll
    for (int rp = 0; rp < 8; rp++)
        #pragma unroll
        for (int cc = 0; cc < 4; cc++)
            wreg[rp][cc] = sWz[half*8 + rp][4*u + cc];
    // bias carried by half 0 only
    ull bzq[4];
    #pragma unroll
    for (int cc = 0; cc < 4; cc++)
        bzq[cc] = half ? 0ULL : pack2(bl[cc*20 + u], 0.0f);

    // owned vehicles: 4g + 2p + half, p in {0,1}
    float c2[2];
    #pragma unroll
    for (int p = 0; p < 2; p++)
        c2[p] = hs[(size_t)NVEH*20 + (size_t)(vb + 4*g + 2*p + half)*20 + u];

    const size_t LC_BASE = (size_t)NVEH * NT;
    const size_t H_BASE  = (size_t)NVEH * NT * 4;
    const size_t C_BASE  = H_BASE + (size_t)NVEH * 20;

    const float* lfx = lf + ((size_t)(vb + d) * NT) * 12 + 4*xc;
    const float* ttx = tt + (size_t)(vb + d) * NT;
    float* outlc = out + LC_BASE + (size_t)(vb + d) * NT * 3;

    #pragma unroll 1
    for (int t = 0; t < NT; t++){
        const int cur = t & 1, nxt = cur ^ 1;

        // ---- loaders: fetch + transform x(t+1) ----
        float4 xo;
        const bool havex = is_loader && (t + 1 < NT);
        if (havex){
            const float4 e = *reinterpret_cast<const float4*>(lfx + (size_t)(t+1)*12);
            float pos = (xc < 2) ? ttx[t+1] : 0.0f;
            xo = xform(e, pos, xc);
        }

        // ---- dense(10)+relu + lc(3) for step t-1 ----
        if (t > 0 && is_dense){
            const ull* hp = reinterpret_cast<const ull*>(&sX[cur][d][12]);
            ull a2[5];
            #pragma unroll
            for (int cc = 0; cc < 5; cc++) a2[cc] = 0ULL;
            #pragma unroll
            for (int rp = 0; rp < 10; rp++){
                ull hm = hp[rp];
                #pragma unroll
                for (int cc = 0; cc < 5; cc++)
                    a2[cc] = fma2(sWdP[rp][dh*5 + cc], hm, a2[cc]);
            }
            float d5[5];
            #pragma unroll
            for (int cc = 0; cc < 5; cc++)
                d5[cc] = fmaxf(hadd2(a2[cc]) + sbd[dh*5 + cc], 0.0f);
            unsigned msk = __activemask();
            float dof[5];
            #pragma unroll
            for (int cc = 0; cc < 5; cc++)
                dof[cc] = __shfl_sync(msk, d5[cc], dpartner);
            if (dh == 0){
                #pragma unroll
                for (int o = 0; o < 3; o++){
                    float acc = sblc[o];
                    #pragma unroll
                    for (int m = 0; m < 5; m++){
                        acc = fmaf(d5[m],  sWlc[m*3 + o],     acc);
                        acc = fmaf(dof[m], sWlc[(5+m)*3 + o], acc);
                    }
                    outlc[(size_t)(t-1)*3 + o] = acc;
                }
            }
        }

        // ---- z for 4 vehicles in 2 passes of 2; k-split halves + shfl combine ----
        #pragma unroll
        for (int p = 0; p < 2; p++){
            const int v0 = 4*g + 2*p;
            const ulonglong2* r0 = reinterpret_cast<const ulonglong2*>(&sX[cur][v0][half*16]);
            const ulonglong2* r1 = reinterpret_cast<const ulonglong2*>(&sX[cur][v0+1][half*16]);
            ull a0 = bzq[0], a1 = bzq[1], a2q = bzq[2], a3 = bzq[3];   // veh v0
            ull b0 = bzq[0], b1 = bzq[1], b2q = bzq[2], b3 = bzq[3];   // veh v0+1
            #pragma unroll
            for (int jj = 0; jj < 4; jj++){
                ulonglong2 m0 = r0[jj];
                ulonglong2 m1 = r1[jj];
                a0  = fma2(wreg[2*jj][0],   m0.x, a0);
                a1  = fma2(wreg[2*jj][1],   m0.x, a1);
                a2q = fma2(wreg[2*jj][2],   m0.x, a2q);
                a3  = fma2(wreg[2*jj][3],   m0.x, a3);
                a0  = fma2(wreg[2*jj+1][0], m0.y, a0);
                a1  = fma2(wreg[2*jj+1][1], m0.y, a1);
                a2q = fma2(wreg[2*jj+1][2], m0.y, a2q);
                a3  = fma2(wreg[2*jj+1][3], m0.y, a3);
                b0  = fma2(wreg[2*jj][0],   m1.x, b0);
                b1  = fma2(wreg[2*jj][1],   m1.x, b1);
                b2q = fma2(wreg[2*jj][2],   m1.x, b2q);
                b3  = fma2(wreg[2*jj][3],   m1.x, b3);
                b0  = fma2(wreg[2*jj+1][0], m1.y, b0);
                b1  = fma2(wreg[2*jj+1][1], m1.y, b1);
                b2q = fma2(wreg[2*jj+1][2], m1.y, b2q);
                b3  = fma2(wreg[2*jj+1][3], m1.y, b3);
            }
            float za[4] = { hadd2(a0), hadd2(a1), hadd2(a2q), hadd2(a3) };
            float zb[4] = { hadd2(b0), hadd2(b1), hadd2(b2q), hadd2(b3) };
            // this lane owns veh v0+half; partner partials arrive via shfl_xor(1)
            float zfull[4];
            #pragma unroll
            for (int cc = 0; cc < 4; cc++){
                float mine = half ? zb[cc] : za[cc];
                float send = half ? za[cc] : zb[cc];
                zfull[cc] = mine + __shfl_xor_sync(0xffffffffu, send, 1);
            }
            float ai = sigt(zfull[0]);
            float af = sigt(zfull[1]);
            float ag = tanh_f(zfull[2]);
            float ao = sigt(zfull[3]);
            float cn = fmaf(af, c2[p], ai * ag);
            c2[p] = cn;
            float hv = ao * tanh_f(cn);
            sX[nxt][v0 + half][12 + u] = hv;       // publish h(t)
        }

        // ---- stage x(t+1) ----
        if (havex) *reinterpret_cast<float4*>(&sX[nxt][d][4*xc]) = xo;

        __syncthreads();
    }

    // ---- epilogue: dense/lc for t = NT-1 (h(511) is in buf[0], NT even) ----
    if (is_dense){
        const ull* hp = reinterpret_cast<const ull*>(&sX[0][d][12]);
        ull a2[5];
        #pragma unroll
        for (int cc = 0; cc < 5; cc++) a2[cc] = 0ULL;
        #pragma unroll
        for (int rp = 0; rp < 10; rp++){
            ull hm = hp[rp];
            #pragma unroll
            for (int cc = 0; cc < 5; cc++)
                a2[cc] = fma2(sWdP[rp][dh*5 + cc], hm, a2[cc]);
        }
        float d5[5];
        #pragma unroll
        for (int cc = 0; cc < 5; cc++)
            d5[cc] = fmaxf(hadd2(a2[cc]) + sbd[dh*5 + cc], 0.0f);
        unsigned msk = __activemask();
        float dof[5];
        #pragma unroll
        for (int cc = 0; cc < 5; cc++)
            dof[cc] = __shfl_sync(msk, d5[cc], dpartner);
        if (dh == 0){
            #pragma unroll
            for (int o = 0; o < 3; o++){
                float acc = sblc[o];
                #pragma unroll
                for (int m = 0; m < 5; m++){
                    acc = fmaf(d5[m],  sWlc[m*3 + o],     acc);
                    acc = fmaf(dof[m], sWlc[(5+m)*3 + o], acc);
                }
                outlc[(size_t)(NT-1)*3 + o] = acc;
            }
        }
    }

    // ---- final states: owned vehicles 4g+half, 4g+2+half ----
    #pragma unroll
    for (int p = 0; p < 2; p++){
        size_t v = (size_t)(vb + 4*g + 2*p + half);
        out[H_BASE + v*20 + u] = sX[0][4*g + 2*p + half][12 + u];
        out[C_BASE + v*20 + u] = c2[p];
    }
}

extern "C" void kernel_launch(void* const* d_in, const int* in_sizes, int n_in,
                              void* d_out, int out_size)
{
    const float* lf  = (const float*)d_in[0];
    const float* tt  = (const float*)d_in[1];
    const float* hs  = (const float*)d_in[2];
    const float* Wk  = (const float*)d_in[3];
    const float* Wr  = (const float*)d_in[4];
    const float* bl  = (const float*)d_in[5];
    const float* Wd  = (const float*)d_in[6];
    const float* bd  = (const float*)d_in[7];
    const float* Wlc = (const float*)d_in[8];
    const float* blc = (const float*)d_in[9];
    float* out = (float*)d_out;

    // output region 0: exact copy of true_traj
    cudaMemcpyAsync(out, tt, (size_t)NVEH * NT * sizeof(float),
                    cudaMemcpyDeviceToDevice);

    lstm_kernel<<<GRID, TPB>>>(lf, tt, hs, Wk, Wr, bl, Wd, bd, Wlc, blc, out);
}

// round 14
// speedup vs baseline: 1.4660x; 1.4660x over previous
#include <cuda_runtime.h>
#include <cuda_fp16.h>
#include <math.h>

#define NVEH 8192
#define NT   512
#define VPC  32           // vehicles per CTA
#define TPB  320          // (20 units x 8 groups) x 2 k-halves
#define HSTR 24           // smem h row stride (floats): [h0..h9|pad2|h10..h19|pad2]
#define GRID (NVEH / VPC) // 256
#define PP_T 8            // timesteps per pre-pass block

typedef unsigned long long ull;

// zx scratch: fp16, layout [v][t][80], col cp = u*4 + gate
__device__ __half g_zx[(size_t)NVEH * NT * 80];

// ---------------- packed f32x2 helpers (sm_103a) ----------------
__device__ __forceinline__ ull fma2(ull a, ull b, ull c){
    ull d;
    asm("fma.rn.f32x2 %0, %1, %2, %3;" : "=l"(d) : "l"(a), "l"(b), "l"(c));
    return d;
}
__device__ __forceinline__ ull pack2(float a, float b){
    ull d; asm("mov.b64 %0, {%1, %2};" : "=l"(d) : "f"(a), "f"(b)); return d;
}
__device__ __forceinline__ float2 unpack2(ull a){
    float2 r; asm("mov.b64 {%0, %1}, %2;" : "=f"(r.x), "=f"(r.y) : "l"(a)); return r;
}
__device__ __forceinline__ float hadd2(ull a){
    float2 r = unpack2(a); return r.x + r.y;
}

// ---------------- activations: single-MUFU tanh ----------------
__device__ __forceinline__ float tanh_f(float x){
    float y; asm("tanh.approx.f32 %0, %1;" : "=f"(y) : "f"(x)); return y;
}
__device__ __forceinline__ float sigt(float x){
    return fmaf(0.5f, tanh_f(0.5f * x), 0.5f);
}
__device__ __forceinline__ float nanfix(float x){
    unsigned uu = __float_as_uint(x);
    return ((uu & 0x7fffffffu) > 0x7f800000u) ? 1.0f : x;
}

// transform one raw float4 chunk of leadfol input into model features
__device__ __forceinline__ float4 xform(float4 e, float pos, int xc){
    float4 xo;
    if (xc == 0){
        xo.x = (e.x - pos) * 0.01f; xo.y = (e.y - pos) * 0.01f;
        xo.z = (e.z - pos) * 0.01f; xo.w = (pos - e.w) * 0.01f;
    } else if (xc == 1){
        xo.x = (pos - e.x) * 0.01f; xo.y = (pos - e.y) * 0.01f;
        xo.z = e.z * 0.025f;        xo.w = e.w * 0.025f;
    } else {
        xo.x = e.x * 0.025f; xo.y = e.y * 0.025f;
        xo.z = e.z * 0.025f; xo.w = e.w * 0.025f;
    }
    xo.x = nanfix(xo.x); xo.y = nanfix(xo.y);
    xo.z = nanfix(xo.z); xo.w = nanfix(xo.w);
    return xo;
}

// ============ pre-pass: g_zx[v][t][cp] = fp16( bl + x(v,t) @ Wk ) ============
__global__ __launch_bounds__(640)
void prepass_kernel(const float* __restrict__ lf,
                    const float* __restrict__ tt,
                    const float* __restrict__ Wk,
                    const float* __restrict__ bl)
{
    __shared__ ull   sWkP[6][80];   // x rowpairs packed, col cp = u*4 + gate
    __shared__ float sblp[80];

    const int tid = threadIdx.x;
    for (int idx = tid; idx < 6*80; idx += 640){
        int rp = idx / 80, cp = idx % 80;
        int uu = cp >> 2, gg = cp & 3;
        int oc = gg*20 + uu;
        sWkP[rp][cp] = pack2(Wk[(2*rp)*80 + oc], Wk[(2*rp+1)*80 + oc]);
    }
    for (int idx = tid; idx < 80; idx += 640){
        int uu = idx >> 2, gg = idx & 3;
        sblp[idx] = bl[gg*20 + uu];
    }
    __syncthreads();

    const int vin = tid / 20;        // 0..31
    const int uu  = tid % 20;        // cols 4uu..4uu+3
    const int v   = blockIdx.y * 32 + vin;

    ull wk[6][4];
    #pragma unroll
    for (int rp = 0; rp < 6; rp++)
        #pragma unroll
        for (int cc = 0; cc < 4; cc++)
            wk[rp][cc] = sWkP[rp][4*uu + cc];
    float bz[4];
    #pragma unroll
    for (int cc = 0; cc < 4; cc++) bz[cc] = sblp[4*uu + cc];

    const float* lfv = lf + (size_t)v * NT * 12;
    const float* ttv = tt + (size_t)v * NT;
    __half* zrow = g_zx + (size_t)v * NT * 80 + 4*uu;

    #pragma unroll 1
    for (int t8 = 0; t8 < PP_T; t8++){
        int t = blockIdx.x * PP_T + t8;
        const float4* xe = reinterpret_cast<const float4*>(lfv + (size_t)t*12);
        float4 e0 = xe[0], e1 = xe[1], e2 = xe[2];
        float pos = ttv[t];
        float4 x0 = xform(e0, pos, 0);
        float4 x1 = xform(e1, pos, 1);
        float4 x2 = xform(e2, pos, 2);
        ull m[6] = { pack2(x0.x, x0.y), pack2(x0.z, x0.w),
                     pack2(x1.x, x1.y), pack2(x1.z, x1.w),
                     pack2(x2.x, x2.y), pack2(x2.z, x2.w) };
        ull acc[4] = {0ULL, 0ULL, 0ULL, 0ULL};
        #pragma unroll
        for (int rp = 0; rp < 6; rp++)
            #pragma unroll
            for (int cc = 0; cc < 4; cc++)
                acc[cc] = fma2(wk[rp][cc], m[rp], acc[cc]);
        float z0 = hadd2(acc[0]) + bz[0];
        float z1 = hadd2(acc[1]) + bz[1];
        float z2 = hadd2(acc[2]) + bz[2];
        float z3 = hadd2(acc[3]) + bz[3];
        __half2 lo = __floats2half2_rn(z0, z1);
        __half2 hi = __floats2half2_rn(z2, z3);
        uint2 st;
        st.x = *reinterpret_cast<unsigned*>(&lo);
        st.y = *reinterpret_cast<unsigned*>(&hi);
        *reinterpret_cast<uint2*>(zrow + (size_t)t*80) = st;
    }
}

// ============ recurrent loop: z = zx + h @ Wr ============
__global__ __launch_bounds__(TPB, 2)
void lstm_kernel(
    const float* __restrict__ hs,   // (2,8192,20)
    const float* __restrict__ Wr,   // (20,80)
    const float* __restrict__ Wd,   // (20,10)
    const float* __restrict__ bd,   // (10)
    const float* __restrict__ Wlc,  // (10,3)
    const float* __restrict__ blc,  // (3)
    float* __restrict__ out)
{
    __shared__ float sH[2][VPC][HSTR];   // h rows, padded halves
    __shared__ ull   sWz[10][80];        // packed h-rowpair weights
    __shared__ ull   sWdP[10][10];       // packed dense weights [rowpair][col]
    __shared__ float sbd[10];
    __shared__ float sWlc[30];
    __shared__ float sblc[3];

    const int tid = threadIdx.x;
    const int blk = blockIdx.x;
    const int vb  = blk * VPC;

    // zero h buffers (pads)
    for (int idx = tid; idx < 2*VPC*HSTR; idx += TPB)
        (&sH[0][0][0])[idx] = 0.0f;

    // weights: rows i = half*5 + rpl  <->  Wr rows (10*half + 2*rpl, +1)
    for (int idx = tid; idx < 10*80; idx += TPB){
        int i = idx / 80, cp = idx % 80;
        int uu = cp >> 2, gg = cp & 3;
        int oc = gg*20 + uu;
        int hh = i / 5, rpl = i % 5;
        int k0 = 10*hh + 2*rpl;
        sWz[i][cp] = pack2(Wr[k0*80 + oc], Wr[(k0+1)*80 + oc]);
    }
    for (int idx = tid; idx < 100; idx += TPB){
        int rp = idx / 10, cc = idx % 10;
        sWdP[rp][cc] = pack2(Wd[(2*rp)*10 + cc], Wd[(2*rp+1)*10 + cc]);
    }
    for (int idx = tid; idx < 10; idx += TPB) sbd[idx]  = bd[idx];
    for (int idx = tid; idx < 30; idx += TPB) sWlc[idx] = Wlc[idx];
    for (int idx = tid; idx < 3;  idx += TPB) sblc[idx] = blc[idx];
    // initial h into buf0 (padded layout)
    for (int idx = tid; idx < VPC*20; idx += TPB){
        int v = idx / 20, k = idx % 20;
        sH[0][v][(k < 10) ? k : k + 2] = hs[((size_t)(vb + v))*20 + k];
    }
    __syncthreads();

    // ---- identities ----
    const int half = tid & 1;        // k-half: 0 -> h rows 0..9, 1 -> 10..19
    const int s    = tid >> 1;       // slot 0..159
    const int u    = s % 20;         // unit
    const int g    = s / 20;         // vehicle group 0..7
    const int uoff = (u < 10) ? u : u + 2;   // padded h offset for unit u
    // dense: 2 threads per vehicle (tid in [96,160))
    const int  dt = tid - 96;
    const int  dv = (dt >= 0) ? (dt >> 1) : 0;
    const int  dh = dt & 1;
    const bool is_dense = (dt >= 0 && dt < 64);

    // ---- h weights in registers (20 b64) ----
    ull wreg[5][4];
    #pragma unroll
    for (int rpl = 0; rpl < 5; rpl++)
        #pragma unroll
        for (int cc = 0; cc < 4; cc++)
            wreg[rpl][cc] = sWz[half*5 + rpl][4*u + cc];

    // owned vehicles: 4g + 2p + half, p in {0,1}
    float c2[2];
    #pragma unroll
    for (int p = 0; p < 2; p++)
        c2[p] = hs[(size_t)NVEH*20 + (size_t)(vb + 4*g + 2*p + half)*20 + u];

    const size_t LC_BASE = (size_t)NVEH * NT;
    const size_t H_BASE  = (size_t)NVEH * NT * 4;
    const size_t C_BASE  = H_BASE + (size_t)NVEH * 20;
    float* outlc = out + LC_BASE + (size_t)(vb + dv) * NT * 3;

    // zx streams for the 2 owned vehicles
    const __half* zp0 = g_zx + (size_t)(vb + 4*g + 0 + half) * NT * 80 + 4*u;
    const __half* zp1 = g_zx + (size_t)(vb + 4*g + 2 + half) * NT * 80 + 4*u;
    uint2 zc0 = *reinterpret_cast<const uint2*>(zp0);
    uint2 zc1 = *reinterpret_cast<const uint2*>(zp1);

    #pragma unroll 1
    for (int t = 0; t < NT; t++){
        const int cur = t & 1, nxt = cur ^ 1;

        // prefetch zx(t+1) (clamped; value unused at t = NT-1)
        const size_t tn = (size_t)((t + 1 < NT) ? (t + 1) : t) * 80;
        uint2 zn0 = *reinterpret_cast<const uint2*>(zp0 + tn);
        uint2 zn1 = *reinterpret_cast<const uint2*>(zp1 + tn);

        // ---- dense(10)+relu + lc(3) for step t-1 ----
        if (t > 0 && is_dense){
            const ull* hp = reinterpret_cast<const ull*>(&sH[cur][dv][0]);
            ull a2[5];
            #pragma unroll
            for (int cc = 0; cc < 5; cc++) a2[cc] = 0ULL;
            #pragma unroll
            for (int rp = 0; rp < 10; rp++){
                ull hm = hp[(rp < 5) ? rp : rp + 1];   // skip pad ull
                #pragma unroll
                for (int cc = 0; cc < 5; cc++)
                    a2[cc] = fma2(sWdP[rp][dh*5 + cc], hm, a2[cc]);
            }
            float d5[5];
            #pragma unroll
            for (int cc = 0; cc < 5; cc++)
                d5[cc] = fmaxf(hadd2(a2[cc]) + sbd[dh*5 + cc], 0.0f);
            unsigned msk = __activemask();
            float dof[5];
            #pragma unroll
            for (int cc = 0; cc < 5; cc++)
                dof[cc] = __shfl_xor_sync(msk, d5[cc], 1);
            if (dh == 0){
                #pragma unroll
                for (int o = 0; o < 3; o++){
                    float acc = sblc[o];
                    #pragma unroll
                    for (int m = 0; m < 5; m++){
                        acc = fmaf(d5[m],  sWlc[m*3 + o],     acc);
                        acc = fmaf(dof[m], sWlc[(5+m)*3 + o], acc);
                    }
                    outlc[(size_t)(t-1)*3 + o] = acc;
                }
            }
        }

        // ---- z = zx + h@Wr for 4 vehicles in 2 passes of 2 ----
        #pragma unroll
        for (int p = 0; p < 2; p++){
            const int v0 = 4*g + 2*p;
            const ull* r0 = reinterpret_cast<const ull*>(&sH[cur][v0][0])   + half*6;
            const ull* r1 = reinterpret_cast<const ull*>(&sH[cur][v0+1][0]) + half*6;
            ull a0 = 0, a1 = 0, a2q = 0, a3 = 0;   // veh v0 partials
            ull b0 = 0, b1 = 0, b2q = 0, b3 = 0;   // veh v0+1 partials
            #pragma unroll
            for (int rp = 0; rp < 5; rp++){
                ull m0 = r0[rp];
                ull m1 = r1[rp];
                a0  = fma2(wreg[rp][0], m0, a0);
                a1  = fma2(wreg[rp][1], m0, a1);
                a2q = fma2(wreg[rp][2], m0, a2q);
                a3  = fma2(wreg[rp][3], m0, a3);
                b0  = fma2(wreg[rp][0], m1, b0);
                b1  = fma2(wreg[rp][1], m1, b1);
                b2q = fma2(wreg[rp][2], m1, b2q);
                b3  = fma2(wreg[rp][3], m1, b3);
            }
            float za[4] = { hadd2(a0), hadd2(a1), hadd2(a2q), hadd2(a3) };
            float zb[4] = { hadd2(b0), hadd2(b1), hadd2(b2q), hadd2(b3) };
            // zx for owned vehicle (v0 + half)
            uint2 zcp = p ? zc1 : zc0;
            __half2 hlo = *reinterpret_cast<__half2*>(&zcp.x);
            __half2 hhi = *reinterpret_cast<__half2*>(&zcp.y);
            float2 f01 = __half22float2(hlo);
            float2 f23 = __half22float2(hhi);
            float zxv[4] = { f01.x, f01.y, f23.x, f23.y };
            float zfull[4];
            #pragma unroll
            for (int cc = 0; cc < 4; cc++){
                float mine = half ? zb[cc] : za[cc];
                float send = half ? za[cc] : zb[cc];
                zfull[cc] = mine + __shfl_xor_sync(0xffffffffu, send, 1) + zxv[cc];
            }
            float ai = sigt(zfull[0]);
            float af = sigt(zfull[1]);
            float ag = tanh_f(zfull[2]);
            float ao = sigt(zfull[3]);
            float cn = fmaf(af, c2[p], ai * ag);
            c2[p] = cn;
            float hv = ao * tanh_f(cn);
            sH[nxt][v0 + half][uoff] = hv;         // publish h(t)
        }

        zc0 = zn0;
        zc1 = zn1;
        __syncthreads();
    }

    // ---- epilogue: dense/lc for t = NT-1 (h(511) in buf[0], NT even) ----
    if (is_dense){
        const ull* hp = reinterpret_cast<const ull*>(&sH[0][dv][0]);
        ull a2[5];
        #pragma unroll
        for (int cc = 0; cc < 5; cc++) a2[cc] = 0ULL;
        #pragma unroll
        for (int rp = 0; rp < 10; rp++){
            ull hm = hp[(rp < 5) ? rp : rp + 1];
            #pragma unroll
            for (int cc = 0; cc < 5; cc++)
                a2[cc] = fma2(sWdP[rp][dh*5 + cc], hm, a2[cc]);
        }
        float d5[5];
        #pragma unroll
        for (int cc = 0; cc < 5; cc++)
            d5[cc] = fmaxf(hadd2(a2[cc]) + sbd[dh*5 + cc], 0.0f);
        unsigned msk = __activemask();
        float dof[5];
        #pragma unroll
        for (int cc = 0; cc < 5; cc++)
            dof[cc] = __shfl_xor_sync(msk, d5[cc], 1);
        if (dh == 0){
            #pragma unroll
            for (int o = 0; o < 3; o++){
                float acc = sblc[o];
                #pragma unroll
                for (int m = 0; m < 5; m++){
                    acc = fmaf(d5[m],  sWlc[m*3 + o],     acc);
                    acc = fmaf(dof[m], sWlc[(5+m)*3 + o], acc);
                }
                outlc[(size_t)(NT-1)*3 + o] = acc;
            }
        }
    }

    // ---- final states ----
    #pragma unroll
    for (int p = 0; p < 2; p++){
        size_t v = (size_t)(vb + 4*g + 2*p + half);
        out[H_BASE + v*20 + u] = sH[0][4*g + 2*p + half][uoff];
        out[C_BASE + v*20 + u] = c2[p];
    }
}

extern "C" void kernel_launch(void* const* d_in, const int* in_sizes, int n_in,
                              void* d_out, int out_size)
{
    const float* lf  = (const float*)d_in[0];
    const float* tt  = (const float*)d_in[1];
    const float* hs  = (const float*)d_in[2];
    const float* Wk  = (const float*)d_in[3];
    const float* Wr  = (const float*)d_in[4];
    const float* bl  = (const float*)d_in[5];
    const float* Wd  = (const float*)d_in[6];
    const float* bd  = (const float*)d_in[7];
    const float* Wlc = (const float*)d_in[8];
    const float* blc = (const float*)d_in[9];
    float* out = (float*)d_out;

    // output region 0: exact copy of true_traj
    cudaMemcpyAsync(out, tt, (size_t)NVEH * NT * sizeof(float),
                    cudaMemcpyDeviceToDevice);

    // pre-pass: zx = b + x @ Wk for all (veh, t)
    prepass_kernel<<<dim3(NT / PP_T, NVEH / 32), 640>>>(lf, tt, Wk, bl);

    // recurrent loop
    lstm_kernel<<<GRID, TPB>>>(hs, Wr, Wd, bd, Wlc, blc, out);
}

// round 15
// speedup vs baseline: 1.4762x; 1.0070x over previous
#include <cuda_runtime.h>
#include <cuda_fp16.h>
#include <math.h>

#define NVEH 8192
#define NT   512
#define VPC  32           // vehicles per CTA (loop)
#define TPB  320          // (20 units x 8 groups) x 2 k-halves
#define HSTR 24           // smem h row stride (floats): [h0..h9|pad2|h10..h19|pad2]
#define GRID (NVEH / VPC) // 256
// pre-pass geometry
#define PPB  320          // 8 vehicles x 40 threads
#define PPV  8
#define PP_T 32

typedef unsigned long long ull;

// zx scratch: fp16, layout [v][t][80], col cp = u*4 + gate
__device__ __half g_zx[(size_t)NVEH * NT * 80];

// ---------------- packed f32x2 helpers (sm_103a) ----------------
__device__ __forceinline__ ull fma2(ull a, ull b, ull c){
    ull d;
    asm("fma.rn.f32x2 %0, %1, %2, %3;" : "=l"(d) : "l"(a), "l"(b), "l"(c));
    return d;
}
__device__ __forceinline__ ull pack2(float a, float b){
    ull d; asm("mov.b64 %0, {%1, %2};" : "=l"(d) : "f"(a), "f"(b)); return d;
}
__device__ __forceinline__ float2 unpack2(ull a){
    float2 r; asm("mov.b64 {%0, %1}, %2;" : "=f"(r.x), "=f"(r.y) : "l"(a)); return r;
}
__device__ __forceinline__ float hadd2(ull a){
    float2 r = unpack2(a); return r.x + r.y;
}

// ---------------- activations: single-MUFU tanh ----------------
__device__ __forceinline__ float tanh_f(float x){
    float y; asm("tanh.approx.f32 %0, %1;" : "=f"(y) : "f"(x)); return y;
}
__device__ __forceinline__ float sigt(float x){
    return fmaf(0.5f, tanh_f(0.5f * x), 0.5f);
}
__device__ __forceinline__ float nanfix(float x){
    unsigned uu = __float_as_uint(x);
    return ((uu & 0x7fffffffu) > 0x7f800000u) ? 1.0f : x;
}

// transform one raw float4 chunk of leadfol input into model features
__device__ __forceinline__ float4 xform(float4 e, float pos, int xc){
    float4 xo;
    if (xc == 0){
        xo.x = (e.x - pos) * 0.01f; xo.y = (e.y - pos) * 0.01f;
        xo.z = (e.z - pos) * 0.01f; xo.w = (pos - e.w) * 0.01f;
    } else if (xc == 1){
        xo.x = (pos - e.x) * 0.01f; xo.y = (pos - e.y) * 0.01f;
        xo.z = e.z * 0.025f;        xo.w = e.w * 0.025f;
    } else {
        xo.x = e.x * 0.025f; xo.y = e.y * 0.025f;
        xo.z = e.z * 0.025f; xo.w = e.w * 0.025f;
    }
    xo.x = nanfix(xo.x); xo.y = nanfix(xo.y);
    xo.z = nanfix(xo.z); xo.w = nanfix(xo.w);
    return xo;
}

// ============ pre-pass: g_zx[v][t][cp] = fp16( bl + x(v,t) @ Wk ) ============
// Also copies true_traj into out region 0 (replaces the memcpy graph node).
__global__ void prepass_kernel(const float* __restrict__ lf,
                               const float* __restrict__ tt,
                               const float* __restrict__ Wk,
                               const float* __restrict__ bl,
                               float* __restrict__ out)
{
    __shared__ ull   sWkP[6][80];   // x rowpairs packed, col cp = u*4 + gate
    __shared__ float sblp[80];

    const int tid = threadIdx.x;
    for (int idx = tid; idx < 6*80; idx += PPB){
        int rp = idx / 80, cp = idx % 80;
        int uu = cp >> 2, gg = cp & 3;
        int oc = gg*20 + uu;
        sWkP[rp][cp] = pack2(Wk[(2*rp)*80 + oc], Wk[(2*rp+1)*80 + oc]);
    }
    for (int idx = tid; idx < 80; idx += PPB){
        int uu = idx >> 2, gg = idx & 3;
        sblp[idx] = bl[gg*20 + uu];
    }
    __syncthreads();

    const int vin = tid / 40;        // vehicle within CTA (0..7)
    const int cpp = tid % 40;        // col-pair: cols 2*cpp, 2*cpp+1
    const int v   = blockIdx.y * PPV + vin;
    const int t0  = blockIdx.x * PP_T;

    ull wk[6][2];
    #pragma unroll
    for (int rp = 0; rp < 6; rp++){
        wk[rp][0] = sWkP[rp][2*cpp];
        wk[rp][1] = sWkP[rp][2*cpp + 1];
    }
    const float bz0 = sblp[2*cpp];
    const float bz1 = sblp[2*cpp + 1];

    const float* lfv  = lf + (size_t)v * NT * 12;
    const float* ttv  = tt + (size_t)v * NT;
    float*       outv = out + (size_t)v * NT;
    __half*      zrow = g_zx + (size_t)v * NT * 80 + 2*cpp;

    #pragma unroll 2
    for (int ti = 0; ti < PP_T; ti++){
        const int t = t0 + ti;
        const float4* xe = reinterpret_cast<const float4*>(lfv + (size_t)t*12);
        float4 e0 = xe[0], e1 = xe[1], e2 = xe[2];
        float pos = ttv[t];
        if (cpp == 0) outv[t] = pos;            // fused true_traj copy
        float4 x0 = xform(e0, pos, 0);
        float4 x1 = xform(e1, pos, 1);
        float4 x2 = xform(e2, pos, 2);
        ull m[6] = { pack2(x0.x, x0.y), pack2(x0.z, x0.w),
                     pack2(x1.x, x1.y), pack2(x1.z, x1.w),
                     pack2(x2.x, x2.y), pack2(x2.z, x2.w) };
        ull a0 = 0ULL, a1 = 0ULL;
        #pragma unroll
        for (int rp = 0; rp < 6; rp++){
            a0 = fma2(wk[rp][0], m[rp], a0);
            a1 = fma2(wk[rp][1], m[rp], a1);
        }
        float z0 = hadd2(a0) + bz0;
        float z1 = hadd2(a1) + bz1;
        __half2 hz = __floats2half2_rn(z0, z1);
        *reinterpret_cast<unsigned*>(zrow + (size_t)t*80) =
            *reinterpret_cast<unsigned*>(&hz);
    }
}

// ============ recurrent loop: z = zx + h @ Wr ============
__global__ __launch_bounds__(TPB, 2)
void lstm_kernel(
    const float* __restrict__ hs,   // (2,8192,20)
    const float* __restrict__ Wr,   // (20,80)
    const float* __restrict__ Wd,   // (20,10)
    const float* __restrict__ bd,   // (10)
    const float* __restrict__ Wlc,  // (10,3)
    const float* __restrict__ blc,  // (3)
    float* __restrict__ out)
{
    __shared__ float sH[2][VPC][HSTR];   // h rows, padded halves
    __shared__ ull   sWz[10][80];        // packed h-rowpair weights
    __shared__ ull   sWdP[10][10];       // packed dense weights [rowpair][col]
    __shared__ float sbd[10];
    __shared__ float sWlc[30];
    __shared__ float sblc[3];

    const int tid = threadIdx.x;
    const int blk = blockIdx.x;
    const int vb  = blk * VPC;

    // zero h buffers (pads)
    for (int idx = tid; idx < 2*VPC*HSTR; idx += TPB)
        (&sH[0][0][0])[idx] = 0.0f;

    // weights: rows i = half*5 + rpl  <->  Wr rows (10*half + 2*rpl, +1)
    for (int idx = tid; idx < 10*80; idx += TPB){
        int i = idx / 80, cp = idx % 80;
        int uu = cp >> 2, gg = cp & 3;
        int oc = gg*20 + uu;
        int hh = i / 5, rpl = i % 5;
        int k0 = 10*hh + 2*rpl;
        sWz[i][cp] = pack2(Wr[k0*80 + oc], Wr[(k0+1)*80 + oc]);
    }
    for (int idx = tid; idx < 100; idx += TPB){
        int rp = idx / 10, cc = idx % 10;
        sWdP[rp][cc] = pack2(Wd[(2*rp)*10 + cc], Wd[(2*rp+1)*10 + cc]);
    }
    for (int idx = tid; idx < 10; idx += TPB) sbd[idx]  = bd[idx];
    for (int idx = tid; idx < 30; idx += TPB) sWlc[idx] = Wlc[idx];
    for (int idx = tid; idx < 3;  idx += TPB) sblc[idx] = blc[idx];
    // initial h into buf0 (padded layout)
    for (int idx = tid; idx < VPC*20; idx += TPB){
        int v = idx / 20, k = idx % 20;
        sH[0][v][(k < 10) ? k : k + 2] = hs[((size_t)(vb + v))*20 + k];
    }
    __syncthreads();

    // ---- identities ----
    const int half = tid & 1;        // k-half: 0 -> h rows 0..9, 1 -> 10..19
    const int s    = tid >> 1;       // slot 0..159
    const int u    = s % 20;         // unit
    const int g    = s / 20;         // vehicle group 0..7
    const int uoff = (u < 10) ? u : u + 2;   // padded h offset for unit u
    // dense: 2 threads per vehicle (tid in [96,160))
    const int  dt = tid - 96;
    const int  dv = (dt >= 0) ? (dt >> 1) : 0;
    const int  dh = dt & 1;
    const bool is_dense = (dt >= 0 && dt < 64);

    // ---- h weights in registers (20 b64) ----
    ull wreg[5][4];
    #pragma unroll
    for (int rpl = 0; rpl < 5; rpl++)
        #pragma unroll
        for (int cc = 0; cc < 4; cc++)
            wreg[rpl][cc] = sWz[half*5 + rpl][4*u + cc];

    // owned vehicles: 4g + 2p + half, p in {0,1}
    float c2[2];
    #pragma unroll
    for (int p = 0; p < 2; p++)
        c2[p] = hs[(size_t)NVEH*20 + (size_t)(vb + 4*g + 2*p + half)*20 + u];

    const size_t LC_BASE = (size_t)NVEH * NT;
    const size_t H_BASE  = (size_t)NVEH * NT * 4;
    const size_t C_BASE  = H_BASE + (size_t)NVEH * 20;
    float* outlc = out + LC_BASE + (size_t)(vb + dv) * NT * 3;

    // zx streams for the 2 owned vehicles
    const __half* zp0 = g_zx + (size_t)(vb + 4*g + 0 + half) * NT * 80 + 4*u;
    const __half* zp1 = g_zx + (size_t)(vb + 4*g + 2 + half) * NT * 80 + 4*u;
    uint2 zc0 = *reinterpret_cast<const uint2*>(zp0);
    uint2 zc1 = *reinterpret_cast<const uint2*>(zp1);

    #pragma unroll 1
    for (int t = 0; t < NT; t++){
        const int cur = t & 1, nxt = cur ^ 1;

        // prefetch zx(t+1) (clamped; value unused at t = NT-1)
        const size_t tn = (size_t)((t + 1 < NT) ? (t + 1) : t) * 80;
        uint2 zn0 = *reinterpret_cast<const uint2*>(zp0 + tn);
        uint2 zn1 = *reinterpret_cast<const uint2*>(zp1 + tn);

        // ---- dense(10)+relu + lc(3) for step t-1 ----
        if (t > 0 && is_dense){
            const ull* hp = reinterpret_cast<const ull*>(&sH[cur][dv][0]);
            ull a2[5];
            #pragma unroll
            for (int cc = 0; cc < 5; cc++) a2[cc] = 0ULL;
            #pragma unroll
            for (int rp = 0; rp < 10; rp++){
                ull hm = hp[(rp < 5) ? rp : rp + 1];   // skip pad ull
                #pragma unroll
                for (int cc = 0; cc < 5; cc++)
                    a2[cc] = fma2(sWdP[rp][dh*5 + cc], hm, a2[cc]);
            }
            float d5[5];
            #pragma unroll
            for (int cc = 0; cc < 5; cc++)
                d5[cc] = fmaxf(hadd2(a2[cc]) + sbd[dh*5 + cc], 0.0f);
            unsigned msk = __activemask();
            float dof[5];
            #pragma unroll
            for (int cc = 0; cc < 5; cc++)
                dof[cc] = __shfl_xor_sync(msk, d5[cc], 1);
            if (dh == 0){
                #pragma unroll
                for (int o = 0; o < 3; o++){
                    float acc = sblc[o];
                    #pragma unroll
                    for (int m = 0; m < 5; m++){
                        acc = fmaf(d5[m],  sWlc[m*3 + o],     acc);
                        acc = fmaf(dof[m], sWlc[(5+m)*3 + o], acc);
                    }
                    outlc[(size_t)(t-1)*3 + o] = acc;
                }
            }
        }

        // ---- z = zx + h@Wr for 4 vehicles in 2 passes of 2 ----
        #pragma unroll
        for (int p = 0; p < 2; p++){
            const int v0 = 4*g + 2*p;
            const ull* r0 = reinterpret_cast<const ull*>(&sH[cur][v0][0])   + half*6;
            const ull* r1 = reinterpret_cast<const ull*>(&sH[cur][v0+1][0]) + half*6;
            ull a0 = 0, a1 = 0, a2q = 0, a3 = 0;   // veh v0 partials
            ull b0 = 0, b1 = 0, b2q = 0, b3 = 0;   // veh v0+1 partials
            #pragma unroll
            for (int rp = 0; rp < 5; rp++){
                ull m0 = r0[rp];
                ull m1 = r1[rp];
                a0  = fma2(wreg[rp][0], m0, a0);
                a1  = fma2(wreg[rp][1], m0, a1);
                a2q = fma2(wreg[rp][2], m0, a2q);
                a3  = fma2(wreg[rp][3], m0, a3);
                b0  = fma2(wreg[rp][0], m1, b0);
                b1  = fma2(wreg[rp][1], m1, b1);
                b2q = fma2(wreg[rp][2], m1, b2q);
                b3  = fma2(wreg[rp][3], m1, b3);
            }
            float za[4] = { hadd2(a0), hadd2(a1), hadd2(a2q), hadd2(a3) };
            float zb[4] = { hadd2(b0), hadd2(b1), hadd2(b2q), hadd2(b3) };
            // zx for owned vehicle (v0 + half)
            uint2 zcp = p ? zc1 : zc0;
            __half2 hlo = *reinterpret_cast<__half2*>(&zcp.x);
            __half2 hhi = *reinterpret_cast<__half2*>(&zcp.y);
            float2 f01 = __half22float2(hlo);
            float2 f23 = __half22float2(hhi);
            float zxv[4] = { f01.x, f01.y, f23.x, f23.y };
            float zfull[4];
            #pragma unroll
            for (int cc = 0; cc < 4; cc++){
                float mine = half ? zb[cc] : za[cc];
                float send = half ? za[cc] : zb[cc];
                zfull[cc] = mine + __shfl_xor_sync(0xffffffffu, send, 1) + zxv[cc];
            }
            float ai = sigt(zfull[0]);
            float af = sigt(zfull[1]);
            float ag = tanh_f(zfull[2]);
            float ao = sigt(zfull[3]);
            float cn = fmaf(af, c2[p], ai * ag);
            c2[p] = cn;
            float hv = ao * tanh_f(cn);
            sH[nxt][v0 + half][uoff] = hv;         // publish h(t)
        }

        zc0 = zn0;
        zc1 = zn1;
        __syncthreads();
    }

    // ---- epilogue: dense/lc for t = NT-1 (h(511) in buf[0], NT even) ----
    if (is_dense){
        const ull* hp = reinterpret_cast<const ull*>(&sH[0][dv][0]);
        ull a2[5];
        #pragma unroll
        for (int cc = 0; cc < 5; cc++) a2[cc] = 0ULL;
        #pragma unroll
        for (int rp = 0; rp < 10; rp++){
            ull hm = hp[(rp < 5) ? rp : rp + 1];
            #pragma unroll
            for (int cc = 0; cc < 5; cc++)
                a2[cc] = fma2(sWdP[rp][dh*5 + cc], hm, a2[cc]);
        }
        float d5[5];
        #pragma unroll
        for (int cc = 0; cc < 5; cc++)
            d5[cc] = fmaxf(hadd2(a2[cc]) + sbd[dh*5 + cc], 0.0f);
        unsigned msk = __activemask();
        float dof[5];
        #pragma unroll
        for (int cc = 0; cc < 5; cc++)
            dof[cc] = __shfl_xor_sync(msk, d5[cc], 1);
        if (dh == 0){
            #pragma unroll
            for (int o = 0; o < 3; o++){
                float acc = sblc[o];
                #pragma unroll
                for (int m = 0; m < 5; m++){
                    acc = fmaf(d5[m],  sWlc[m*3 + o],     acc);
                    acc = fmaf(dof[m], sWlc[(5+m)*3 + o], acc);
                }
                outlc[(size_t)(NT-1)*3 + o] = acc;
            }
        }
    }

    // ---- final states ----
    #pragma unroll
    for (int p = 0; p < 2; p++){
        size_t v = (size_t)(vb + 4*g + 2*p + half);
        out[H_BASE + v*20 + u] = sH[0][4*g + 2*p + half][uoff];
        out[C_BASE + v*20 + u] = c2[p];
    }
}

extern "C" void kernel_launch(void* const* d_in, const int* in_sizes, int n_in,
                              void* d_out, int out_size)
{
    const float* lf  = (const float*)d_in[0];
    const float* tt  = (const float*)d_in[1];
    const float* hs  = (const float*)d_in[2];
    const float* Wk  = (const float*)d_in[3];
    const float* Wr  = (const float*)d_in[4];
    const float* bl  = (const float*)d_in[5];
    const float* Wd  = (const float*)d_in[6];
    const float* bd  = (const float*)d_in[7];
    const float* Wlc = (const float*)d_in[8];
    const float* blc = (const float*)d_in[9];
    float* out = (float*)d_out;

    // pre-pass: zx = b + x @ Wk for all (veh, t); also copies tt -> out region 0
    prepass_kernel<<<dim3(NT / PP_T, NVEH / PPV), PPB>>>(lf, tt, Wk, bl, out);

    // recurrent loop
    lstm_kernel<<<GRID, TPB>>>(hs, Wr, Wd, bd, Wlc, blc, out);
}

// round 16
// speedup vs baseline: 1.5183x; 1.0285x over previous
#include <cuda_runtime.h>
#include <cuda_fp16.h>
#include <math.h>

#define NVEH 8192
#define NT   512
#define VPC  32           // vehicles per CTA (loop)
#define TPB  320          // (20 units x 8 groups) x 2 k-halves
#define HSTR 24           // smem h row stride (floats): [h0..h9|pad2|h10..h19|pad2]
#define GRID (NVEH / VPC) // 256
// pre-pass geometry: 16 vehicles x 20 threads (4 cols each), 16 timesteps/block
#define PPB  320
#define PPV  16
#define PP_T 16

typedef unsigned long long ull;

// zx scratch: fp16, layout [v][t][80], col cp = u*4 + gate
__device__ __half g_zx[(size_t)NVEH * NT * 80];

// ---------------- packed f32x2 helpers (sm_103a) ----------------
__device__ __forceinline__ ull fma2(ull a, ull b, ull c){
    ull d;
    asm("fma.rn.f32x2 %0, %1, %2, %3;" : "=l"(d) : "l"(a), "l"(b), "l"(c));
    return d;
}
__device__ __forceinline__ ull pack2(float a, float b){
    ull d; asm("mov.b64 %0, {%1, %2};" : "=l"(d) : "f"(a), "f"(b)); return d;
}
__device__ __forceinline__ float2 unpack2(ull a){
    float2 r; asm("mov.b64 {%0, %1}, %2;" : "=f"(r.x), "=f"(r.y) : "l"(a)); return r;
}
__device__ __forceinline__ float hadd2(ull a){
    float2 r = unpack2(a); return r.x + r.y;
}

// ---------------- activations: single-MUFU tanh ----------------
__device__ __forceinline__ float tanh_f(float x){
    float y; asm("tanh.approx.f32 %0, %1;" : "=f"(y) : "f"(x)); return y;
}
__device__ __forceinline__ float sigt(float x){
    return fmaf(0.5f, tanh_f(0.5f * x), 0.5f);
}
__device__ __forceinline__ float nanfix(float x){
    unsigned uu = __float_as_uint(x);
    return ((uu & 0x7fffffffu) > 0x7f800000u) ? 1.0f : x;
}

// transform one raw float4 chunk of leadfol input into model features
__device__ __forceinline__ float4 xform(float4 e, float pos, int xc){
    float4 xo;
    if (xc == 0){
        xo.x = (e.x - pos) * 0.01f; xo.y = (e.y - pos) * 0.01f;
        xo.z = (e.z - pos) * 0.01f; xo.w = (pos - e.w) * 0.01f;
    } else if (xc == 1){
        xo.x = (pos - e.x) * 0.01f; xo.y = (pos - e.y) * 0.01f;
        xo.z = e.z * 0.025f;        xo.w = e.w * 0.025f;
    } else {
        xo.x = e.x * 0.025f; xo.y = e.y * 0.025f;
        xo.z = e.z * 0.025f; xo.w = e.w * 0.025f;
    }
    xo.x = nanfix(xo.x); xo.y = nanfix(xo.y);
    xo.z = nanfix(xo.z); xo.w = nanfix(xo.w);
    return xo;
}

// ============ pre-pass: g_zx[v][t][cp] = fp16( bl + x(v,t) @ Wk ) ============
// 20 threads per vehicle, 4 columns each (4x less redundant x traffic).
// Also copies true_traj into out region 0 (replaces the memcpy graph node).
__global__ void prepass_kernel(const float* __restrict__ lf,
                               const float* __restrict__ tt,
                               const float* __restrict__ Wk,
                               const float* __restrict__ bl,
                               float* __restrict__ out)
{
    __shared__ ull   sWkP[6][80];   // x rowpairs packed, col cp = u*4 + gate
    __shared__ float sblp[80];

    const int tid = threadIdx.x;
    for (int idx = tid; idx < 6*80; idx += PPB){
        int rp = idx / 80, cp = idx % 80;
        int uu = cp >> 2, gg = cp & 3;
        int oc = gg*20 + uu;
        sWkP[rp][cp] = pack2(Wk[(2*rp)*80 + oc], Wk[(2*rp+1)*80 + oc]);
    }
    for (int idx = tid; idx < 80; idx += PPB){
        int uu = idx >> 2, gg = idx & 3;
        sblp[idx] = bl[gg*20 + uu];
    }
    __syncthreads();

    const int vin = tid / 20;        // vehicle within CTA (0..15)
    const int cq  = tid % 20;        // owns cols 4cq..4cq+3
    const int v   = blockIdx.y * PPV + vin;
    const int t0  = blockIdx.x * PP_T;

    ull wk[6][4];
    #pragma unroll
    for (int rp = 0; rp < 6; rp++)
        #pragma unroll
        for (int cc = 0; cc < 4; cc++)
            wk[rp][cc] = sWkP[rp][4*cq + cc];
    float bz[4];
    #pragma unroll
    for (int cc = 0; cc < 4; cc++) bz[cc] = sblp[4*cq + cc];

    const float* lfv  = lf + (size_t)v * NT * 12;
    const float* ttv  = tt + (size_t)v * NT;
    float*       outv = out + (size_t)v * NT;
    __half*      zrow = g_zx + (size_t)v * NT * 80 + 4*cq;

    #pragma unroll 2
    for (int ti = 0; ti < PP_T; ti++){
        const int t = t0 + ti;
        const float4* xe = reinterpret_cast<const float4*>(lfv + (size_t)t*12);
        float4 e0 = xe[0], e1 = xe[1], e2 = xe[2];
        float pos = ttv[t];
        if (cq == 0) outv[t] = pos;             // fused true_traj copy
        float4 x0 = xform(e0, pos, 0);
        float4 x1 = xform(e1, pos, 1);
        float4 x2 = xform(e2, pos, 2);
        ull m[6] = { pack2(x0.x, x0.y), pack2(x0.z, x0.w),
                     pack2(x1.x, x1.y), pack2(x1.z, x1.w),
                     pack2(x2.x, x2.y), pack2(x2.z, x2.w) };
        ull acc[4] = {0ULL, 0ULL, 0ULL, 0ULL};
        #pragma unroll
        for (int rp = 0; rp < 6; rp++)
            #pragma unroll
            for (int cc = 0; cc < 4; cc++)
                acc[cc] = fma2(wk[rp][cc], m[rp], acc[cc]);
        float z0 = hadd2(acc[0]) + bz[0];
        float z1 = hadd2(acc[1]) + bz[1];
        float z2 = hadd2(acc[2]) + bz[2];
        float z3 = hadd2(acc[3]) + bz[3];
        __half2 lo = __floats2half2_rn(z0, z1);
        __half2 hi = __floats2half2_rn(z2, z3);
        uint2 st;
        st.x = *reinterpret_cast<unsigned*>(&lo);
        st.y = *reinterpret_cast<unsigned*>(&hi);
        *reinterpret_cast<uint2*>(zrow + (size_t)t*80) = st;   // 8B store
    }
}

// ============ recurrent loop: z = zx + h @ Wr (unchanged from R15) ============
__global__ __launch_bounds__(TPB, 2)
void lstm_kernel(
    const float* __restrict__ hs,   // (2,8192,20)
    const float* __restrict__ Wr,   // (20,80)
    const float* __restrict__ Wd,   // (20,10)
    const float* __restrict__ bd,   // (10)
    const float* __restrict__ Wlc,  // (10,3)
    const float* __restrict__ blc,  // (3)
    float* __restrict__ out)
{
    __shared__ float sH[2][VPC][HSTR];   // h rows, padded halves
    __shared__ ull   sWz[10][80];        // packed h-rowpair weights
    __shared__ ull   sWdP[10][10];       // packed dense weights [rowpair][col]
    __shared__ float sbd[10];
    __shared__ float sWlc[30];
    __shared__ float sblc[3];

    const int tid = threadIdx.x;
    const int blk = blockIdx.x;
    const int vb  = blk * VPC;

    // zero h buffers (pads)
    for (int idx = tid; idx < 2*VPC*HSTR; idx += TPB)
        (&sH[0][0][0])[idx] = 0.0f;

    // weights: rows i = half*5 + rpl  <->  Wr rows (10*half + 2*rpl, +1)
    for (int idx = tid; idx < 10*80; idx += TPB){
        int i = idx / 80, cp = idx % 80;
        int uu = cp >> 2, gg = cp & 3;
        int oc = gg*20 + uu;
        int hh = i / 5, rpl = i % 5;
        int k0 = 10*hh + 2*rpl;
        sWz[i][cp] = pack2(Wr[k0*80 + oc], Wr[(k0+1)*80 + oc]);
    }
    for (int idx = tid; idx < 100; idx += TPB){
        int rp = idx / 10, cc = idx % 10;
        sWdP[rp][cc] = pack2(Wd[(2*rp)*10 + cc], Wd[(2*rp+1)*10 + cc]);
    }
    for (int idx = tid; idx < 10; idx += TPB) sbd[idx]  = bd[idx];
    for (int idx = tid; idx < 30; idx += TPB) sWlc[idx] = Wlc[idx];
    for (int idx = tid; idx < 3;  idx += TPB) sblc[idx] = blc[idx];
    // initial h into buf0 (padded layout)
    for (int idx = tid; idx < VPC*20; idx += TPB){
        int v = idx / 20, k = idx % 20;
        sH[0][v][(k < 10) ? k : k + 2] = hs[((size_t)(vb + v))*20 + k];
    }
    __syncthreads();

    // ---- identities ----
    const int half = tid & 1;        // k-half: 0 -> h rows 0..9, 1 -> 10..19
    const int s    = tid >> 1;       // slot 0..159
    const int u    = s % 20;         // unit
    const int g    = s / 20;         // vehicle group 0..7
    const int uoff = (u < 10) ? u : u + 2;   // padded h offset for unit u
    // dense: 2 threads per vehicle (tid in [96,160))
    const int  dt = tid - 96;
    const int  dv = (dt >= 0) ? (dt >> 1) : 0;
    const int  dh = dt & 1;
    const bool is_dense = (dt >= 0 && dt < 64);

    // ---- h weights in registers (20 b64) ----
    ull wreg[5][4];
    #pragma unroll
    for (int rpl = 0; rpl < 5; rpl++)
        #pragma unroll
        for (int cc = 0; cc < 4; cc++)
            wreg[rpl][cc] = sWz[half*5 + rpl][4*u + cc];

    // owned vehicles: 4g + 2p + half, p in {0,1}
    float c2[2];
    #pragma unroll
    for (int p = 0; p < 2; p++)
        c2[p] = hs[(size_t)NVEH*20 + (size_t)(vb + 4*g + 2*p + half)*20 + u];

    const size_t LC_BASE = (size_t)NVEH * NT;
    const size_t H_BASE  = (size_t)NVEH * NT * 4;
    const size_t C_BASE  = H_BASE + (size_t)NVEH * 20;
    float* outlc = out + LC_BASE + (size_t)(vb + dv) * NT * 3;

    // zx streams for the 2 owned vehicles
    const __half* zp0 = g_zx + (size_t)(vb + 4*g + 0 + half) * NT * 80 + 4*u;
    const __half* zp1 = g_zx + (size_t)(vb + 4*g + 2 + half) * NT * 80 + 4*u;
    uint2 zc0 = *reinterpret_cast<const uint2*>(zp0);
    uint2 zc1 = *reinterpret_cast<const uint2*>(zp1);

    #pragma unroll 1
    for (int t = 0; t < NT; t++){
        const int cur = t & 1, nxt = cur ^ 1;

        // prefetch zx(t+1) (clamped; value unused at t = NT-1)
        const size_t tn = (size_t)((t + 1 < NT) ? (t + 1) : t) * 80;
        uint2 zn0 = *reinterpret_cast<const uint2*>(zp0 + tn);
        uint2 zn1 = *reinterpret_cast<const uint2*>(zp1 + tn);

        // ---- dense(10)+relu + lc(3) for step t-1 ----
        if (t > 0 && is_dense){
            const ull* hp = reinterpret_cast<const ull*>(&sH[cur][dv][0]);
            ull a2[5];
            #pragma unroll
            for (int cc = 0; cc < 5; cc++) a2[cc] = 0ULL;
            #pragma unroll
            for (int rp = 0; rp < 10; rp++){
                ull hm = hp[(rp < 5) ? rp : rp + 1];   // skip pad ull
                #pragma unroll
                for (int cc = 0; cc < 5; cc++)
                    a2[cc] = fma2(sWdP[rp][dh*5 + cc], hm, a2[cc]);
            }
            float d5[5];
            #pragma unroll
            for (int cc = 0; cc < 5; cc++)
                d5[cc] = fmaxf(hadd2(a2[cc]) + sbd[dh*5 + cc], 0.0f);
            unsigned msk = __activemask();
            float dof[5];
            #pragma unroll
            for (int cc = 0; cc < 5; cc++)
                dof[cc] = __shfl_xor_sync(msk, d5[cc], 1);
            if (dh == 0){
                #pragma unroll
                for (int o = 0; o < 3; o++){
                    float acc = sblc[o];
                    #pragma unroll
                    for (int m = 0; m < 5; m++){
                        acc = fmaf(d5[m],  sWlc[m*3 + o],     acc);
                        acc = fmaf(dof[m], sWlc[(5+m)*3 + o], acc);
                    }
                    outlc[(size_t)(t-1)*3 + o] = acc;
                }
            }
        }

        // ---- z = zx + h@Wr for 4 vehicles in 2 passes of 2 ----
        #pragma unroll
        for (int p = 0; p < 2; p++){
            const int v0 = 4*g + 2*p;
            const ull* r0 = reinterpret_cast<const ull*>(&sH[cur][v0][0])   + half*6;
            const ull* r1 = reinterpret_cast<const ull*>(&sH[cur][v0+1][0]) + half*6;
            ull a0 = 0, a1 = 0, a2q = 0, a3 = 0;   // veh v0 partials
            ull b0 = 0, b1 = 0, b2q = 0, b3 = 0;   // veh v0+1 partials
            #pragma unroll
            for (int rp = 0; rp < 5; rp++){
                ull m0 = r0[rp];
                ull m1 = r1[rp];
                a0  = fma2(wreg[rp][0], m0, a0);
                a1  = fma2(wreg[rp][1], m0, a1);
                a2q = fma2(wreg[rp][2], m0, a2q);
                a3  = fma2(wreg[rp][3], m0, a3);
                b0  = fma2(wreg[rp][0], m1, b0);
                b1  = fma2(wreg[rp][1], m1, b1);
                b2q = fma2(wreg[rp][2], m1, b2q);
                b3  = fma2(wreg[rp][3], m1, b3);
            }
            float za[4] = { hadd2(a0), hadd2(a1), hadd2(a2q), hadd2(a3) };
            float zb[4] = { hadd2(b0), hadd2(b1), hadd2(b2q), hadd2(b3) };
            // zx for owned vehicle (v0 + half)
            uint2 zcp = p ? zc1 : zc0;
            __half2 hlo = *reinterpret_cast<__half2*>(&zcp.x);
            __half2 hhi = *reinterpret_cast<__half2*>(&zcp.y);
            float2 f01 = __half22float2(hlo);
            float2 f23 = __half22float2(hhi);
            float zxv[4] = { f01.x, f01.y, f23.x, f23.y };
            float zfull[4];
            #pragma unroll
            for (int cc = 0; cc < 4; cc++){
                float mine = half ? zb[cc] : za[cc];
                float send = half ? za[cc] : zb[cc];
                zfull[cc] = mine + __shfl_xor_sync(0xffffffffu, send, 1) + zxv[cc];
            }
            float ai = sigt(zfull[0]);
            float af = sigt(zfull[1]);
            float ag = tanh_f(zfull[2]);
            float ao = sigt(zfull[3]);
            float cn = fmaf(af, c2[p], ai * ag);
            c2[p] = cn;
            float hv = ao * tanh_f(cn);
            sH[nxt][v0 + half][uoff] = hv;         // publish h(t)
        }

        zc0 = zn0;
        zc1 = zn1;
        __syncthreads();
    }

    // ---- epilogue: dense/lc for t = NT-1 (h(511) in buf[0], NT even) ----
    if (is_dense){
        const ull* hp = reinterpret_cast<const ull*>(&sH[0][dv][0]);
        ull a2[5];
        #pragma unroll
        for (int cc = 0; cc < 5; cc++) a2[cc] = 0ULL;
        #pragma unroll
        for (int rp = 0; rp < 10; rp++){
            ull hm = hp[(rp < 5) ? rp : rp + 1];
            #pragma unroll
            for (int cc = 0; cc < 5; cc++)
                a2[cc] = fma2(sWdP[rp][dh*5 + cc], hm, a2[cc]);
        }
        float d5[5];
        #pragma unroll
        for (int cc = 0; cc < 5; cc++)
            d5[cc] = fmaxf(hadd2(a2[cc]) + sbd[dh*5 + cc], 0.0f);
        unsigned msk = __activemask();
        float dof[5];
        #pragma unroll
        for (int cc = 0; cc < 5; cc++)
            dof[cc] = __shfl_xor_sync(msk, d5[cc], 1);
        if (dh == 0){
            #pragma unroll
            for (int o = 0; o < 3; o++){
                float acc = sblc[o];
                #pragma unroll
                for (int m = 0; m < 5; m++){
                    acc = fmaf(d5[m],  sWlc[m*3 + o],     acc);
                    acc = fmaf(dof[m], sWlc[(5+m)*3 + o], acc);
                }
                outlc[(size_t)(NT-1)*3 + o] = acc;
            }
        }
    }

    // ---- final states ----
    #pragma unroll
    for (int p = 0; p < 2; p++){
        size_t v = (size_t)(vb + 4*g + 2*p + half);
        out[H_BASE + v*20 + u] = sH[0][4*g + 2*p + half][uoff];
        out[C_BASE + v*20 + u] = c2[p];
    }
}

extern "C" void kernel_launch(void* const* d_in, const int* in_sizes, int n_in,
                              void* d_out, int out_size)
{
    const float* lf  = (const float*)d_in[0];
    const float* tt  = (const float*)d_in[1];
    const float* hs  = (const float*)d_in[2];
    const float* Wk  = (const float*)d_in[3];
    const float* Wr  = (const float*)d_in[4];
    const float* bl  = (const float*)d_in[5];
    const float* Wd  = (const float*)d_in[6];
    const float* bd  = (const float*)d_in[7];
    const float* Wlc = (const float*)d_in[8];
    const float* blc = (const float*)d_in[9];
    float* out = (float*)d_out;

    // pre-pass: zx = b + x @ Wk for all (veh, t); also copies tt -> out region 0
    prepass_kernel<<<dim3(NT / PP_T, NVEH / PPV), PPB>>>(lf, tt, Wk, bl, out);

    // recurrent loop
    lstm_kernel<<<GRID, TPB>>>(hs, Wr, Wd, bd, Wlc, blc, out);
}